// round 5
// baseline (speedup 1.0000x reference)
#include <cuda_runtime.h>

// ---------------- problem constants ----------------
#define BB      64          // batch
#define CC      256         // channels
#define HWX     3136        // 56*56
#define G       4           // whitening groups
#define NCH     64          // channels per group
#define MTOT    (BB*HWX)    // 200704 samples per group
#define TS      112         // samples per tile (divides 3136: 28 chunks)
#define CHUNKS  (HWX/TS)    // 28
#define TILESG  (BB*CHUNKS) // 1792 tiles per group
#define NBLK    74          // blocks per group (grid = 296 = 2 per SM)
#define EPSV    1e-5f
#define NS_T    5

// ---------------- device scratch (no allocations allowed) ----------------
__device__ float g_S2[G][NCH][NCH];   // sum of x x^T
__device__ float g_sum[G][NCH];       // sum of x
__device__ float g_wmT[G][NCH*NCH];   // folded whitening matrix, layout [d][c]
__device__ float g_beta[G][NCH];      // folded per-channel offset

// ---------------- zero scratch ----------------
__global__ void zero_kernel() {
    int i = blockIdx.x * blockDim.x + threadIdx.x;
    float* p = &g_S2[0][0][0];
    if (i < G * NCH * NCH) p[i] = 0.0f;
    if (i < G * NCH) (&g_sum[0][0])[i] = 0.0f;
}

// ---------------- phase 1: covariance raw moments ----------------
// grid = G*NBLK, block = 256. Each block: register-resident 4x4 micro-tile of
// the 64x64 S2 accumulator, looped over its share of 112-sample tiles, one
// atomic flush at the end.
__global__ __launch_bounds__(256) void cov_kernel(const float* __restrict__ x) {
    __shared__ float st[TS][68];      // transposed tile [s][c], pad 68 (16B-mult)

    const int gi  = blockIdx.x / NBLK;
    const int blk = blockIdx.x % NBLK;
    const int tid = threadIdx.x;
    const int ig  = tid >> 4;         // 0..15 -> rows ig*4..ig*4+3
    const int jg  = tid & 15;         // 0..15 -> cols jg*4..jg*4+3

    float acc[4][4] = {};
    float sacc[4]   = {0.f, 0.f, 0.f, 0.f};

    const float* xg = x + (size_t)gi * NCH * HWX;

    for (int t = blk; t < TILESG; t += NBLK) {
        const int bb = t / CHUNKS;
        const int cs = (t % CHUNKS) * TS;
        const float* base = xg + (size_t)bb * CC * HWX + cs;

        __syncthreads();   // previous tile fully consumed
        // load 64x112 floats = 1792 float4, 7 per thread, coalesced rows
        #pragma unroll
        for (int i = 0; i < 7; i++) {
            int idx = tid + 256 * i;
            int c   = idx / 28;
            int s4  = (idx % 28) * 4;
            float4 v = *reinterpret_cast<const float4*>(base + c * HWX + s4);
            st[s4 + 0][c] = v.x;
            st[s4 + 1][c] = v.y;
            st[s4 + 2][c] = v.z;
            st[s4 + 3][c] = v.w;
        }
        __syncthreads();

        #pragma unroll 4
        for (int k = 0; k < TS; k++) {
            float4 a = *reinterpret_cast<const float4*>(&st[k][ig * 4]);
            float4 b = *reinterpret_cast<const float4*>(&st[k][jg * 4]);
            float av[4] = {a.x, a.y, a.z, a.w};
            float bv[4] = {b.x, b.y, b.z, b.w};
            #pragma unroll
            for (int r = 0; r < 4; r++)
                #pragma unroll
                for (int q = 0; q < 4; q++)
                    acc[r][q] += av[r] * bv[q];
            if (ig == 0) {            // warp-0 lanes also collect channel sums
                sacc[0] += bv[0]; sacc[1] += bv[1];
                sacc[2] += bv[2]; sacc[3] += bv[3];
            }
        }
    }

    #pragma unroll
    for (int r = 0; r < 4; r++)
        #pragma unroll
        for (int q = 0; q < 4; q++)
            atomicAdd(&g_S2[gi][ig * 4 + r][jg * 4 + q], acc[r][q]);
    if (ig == 0) {
        #pragma unroll
        for (int q = 0; q < 4; q++)
            atomicAdd(&g_sum[gi][jg * 4 + q], sacc[q]);
    }
}

// ---------------- phase 2: Newton-Schulz + folding ----------------
// One block per group, 256 threads, dynamic smem: 4 matrices [64][65] + mean.
__device__ __forceinline__ void mm64(float* O, const float* A, const float* B) {
    const int r  = threadIdx.x >> 2;         // 0..63
    const int cb = (threadIdx.x & 3) << 4;   // 0,16,32,48
    float acc[16] = {};
    for (int k = 0; k < 64; k++) {
        float a = A[r * 65 + k];
        #pragma unroll
        for (int j = 0; j < 16; j++)
            acc[j] += a * B[k * 65 + cb + j];
    }
    #pragma unroll
    for (int j = 0; j < 16; j++)
        O[r * 65 + cb + j] = acc[j];
    __syncthreads();
}

__global__ __launch_bounds__(256) void ns_kernel(const float* __restrict__ weight,
                                                 const float* __restrict__ bias) {
    extern __shared__ float sm[];
    float* Sn   = sm;
    float* P    = sm + 4160;
    float* T1   = sm + 8320;
    float* T2   = sm + 12480;
    float* mean = sm + 16640;    // 64
    float* misc = sm + 16704;    // scalars

    const int gi  = blockIdx.x;
    const int tid = threadIdx.x;
    const int r   = tid >> 2;
    const int cb  = (tid & 3) << 4;

    if (tid < 64) mean[tid] = g_sum[gi][tid] * (1.0f / MTOT);
    __syncthreads();

    // Sigma -> Sn (unscaled for now)
    #pragma unroll
    for (int j = 0; j < 16; j++) {
        int c = cb + j;
        float sig = g_S2[gi][r][c] * (1.0f / MTOT) - mean[r] * mean[c];
        if (r == c) sig += EPSV;
        Sn[r * 65 + c] = sig;
    }
    __syncthreads();

    // trace -> rTr
    if (tid < 32) {
        float ts = Sn[tid * 65 + tid] + Sn[(tid + 32) * 65 + (tid + 32)];
        #pragma unroll
        for (int o = 16; o; o >>= 1) ts += __shfl_xor_sync(0xffffffffu, ts, o);
        if (tid == 0) misc[0] = 1.0f / ts;
    }
    __syncthreads();
    const float rTr = misc[0];

    // Sn *= rTr ; P = I
    #pragma unroll
    for (int j = 0; j < 16; j++) {
        int c = cb + j;
        Sn[r * 65 + c] *= rTr;
        P[r * 65 + c] = (r == c) ? 1.0f : 0.0f;
    }
    __syncthreads();

    for (int it = 0; it < NS_T; it++) {
        mm64(T1, P, P);     // P^2
        mm64(T2, T1, P);    // P^3
        mm64(T1, T2, Sn);   // P^3 Sn
        #pragma unroll
        for (int j = 0; j < 16; j++) {
            int idx = r * 65 + cb + j;
            P[idx] = 1.5f * P[idx] - 0.5f * T1[idx];
        }
        __syncthreads();
    }

    const float s = sqrtf(rTr);
    // fold weight into wm; store transposed layout [d][c]
    #pragma unroll
    for (int j = 0; j < 16; j++) {
        int d = cb + j;
        float w2 = P[r * 65 + d] * s * weight[gi * NCH + r];
        g_wmT[gi][d * NCH + r] = w2;
    }
    // beta[c] = bias[c] - weight[c] * s * sum_d P[c][d]*mean[d]
    if (tid < 64) {
        float off = 0.0f;
        for (int d = 0; d < 64; d++) off += P[tid * 65 + d] * mean[d];
        g_beta[gi][tid] = bias[gi * NCH + tid] - weight[gi * NCH + tid] * s * off;
    }
}

// ---------------- phase 3: whitening apply ----------------
// out[c][s] = sum_d wmT[d][c] * x[d][s] + beta[c]
__global__ __launch_bounds__(256) void whiten_kernel(const float* __restrict__ x,
                                                     float* __restrict__ out) {
    __shared__ float wmT_s[NCH][NCH];   // [d][c]
    __shared__ float beta_s[NCH];
    __shared__ float tile[NCH][116];    // [d][s], pad 116 (16B-mult)

    const int gi  = blockIdx.x / NBLK;
    const int blk = blockIdx.x % NBLK;
    const int tid = threadIdx.x;
    const int ig  = tid >> 4;           // output-channel group: rows ig*4..+3
    const int sg  = tid & 15;           // sample group: 7 samples
    const int soff = sg * 7;

    #pragma unroll
    for (int i = 0; i < 16; i++)
        (&wmT_s[0][0])[tid + 256 * i] = g_wmT[gi][tid + 256 * i];
    if (tid < 64) beta_s[tid] = g_beta[gi][tid];
    __syncthreads();

    const float* xg = x + (size_t)gi * NCH * HWX;
    float* og = out + (size_t)gi * NCH * HWX;

    for (int t = blk; t < TILESG; t += NBLK) {
        const int bb = t / CHUNKS;
        const int cs = (t % CHUNKS) * TS;
        const float* base = xg + (size_t)bb * CC * HWX + cs;

        __syncthreads();
        #pragma unroll
        for (int i = 0; i < 7; i++) {
            int idx = tid + 256 * i;
            int c   = idx / 28;
            int s4  = (idx % 28) * 4;
            float4 v = *reinterpret_cast<const float4*>(base + c * HWX + s4);
            *reinterpret_cast<float4*>(&tile[c][s4]) = v;
        }
        __syncthreads();

        float accv[4][7] = {};
        #pragma unroll 2
        for (int d = 0; d < 64; d++) {
            float4 w = *reinterpret_cast<const float4*>(&wmT_s[d][ig * 4]);
            #pragma unroll
            for (int u = 0; u < 7; u++) {
                float xv = tile[d][soff + u];
                accv[0][u] += w.x * xv;
                accv[1][u] += w.y * xv;
                accv[2][u] += w.z * xv;
                accv[3][u] += w.w * xv;
            }
        }

        float* ob = og + (size_t)bb * CC * HWX + cs;
        #pragma unroll
        for (int rr = 0; rr < 4; rr++) {
            int c = ig * 4 + rr;
            float b = beta_s[c];
            #pragma unroll
            for (int u = 0; u < 7; u++)
                ob[c * HWX + soff + u] = accv[rr][u] + b;
        }
    }
}

// ---------------- launch ----------------
extern "C" void kernel_launch(void* const* d_in, const int* in_sizes, int n_in,
                              void* d_out, int out_size) {
    const float* x      = (const float*)d_in[0];
    const float* weight = (const float*)d_in[1];
    const float* bias   = (const float*)d_in[2];
    float* out          = (float*)d_out;

    // opt-in to >48KB dynamic shared for the NS kernel (idempotent host call)
    const int NS_SMEM = (16704 + 16) * 4;
    cudaFuncSetAttribute(ns_kernel, cudaFuncAttributeMaxDynamicSharedMemorySize,
                         NS_SMEM);

    zero_kernel<<<(G * NCH * NCH + 255) / 256, 256>>>();
    cov_kernel<<<G * NBLK, 256>>>(x);
    ns_kernel<<<G, 256, NS_SMEM>>>(weight, bias);
    whiten_kernel<<<G * NBLK, 256>>>(x, out);
}

// round 7
// speedup vs baseline: 2.1117x; 2.1117x over previous
#include <cuda_runtime.h>
#include <cstdint>

// ---------------- problem constants ----------------
#define BB      64
#define CC      256
#define HWX     3136        // 56*56
#define G       4
#define NCH     64
#define MTOT    (BB*HWX)
#define TSAMP   64          // samples per tile
#define CHUNKS  (HWX/TSAMP) // 49
#define TILESG  (BB*CHUNKS) // 3136 tiles per group
#define NBLK    74          // blocks per group (grid 296 = 2/SM)
#define SPAD    76          // smem row pitch in words (conflict-free both patterns)
#define EPSV    1e-5f
#define NS_T    5

// ---------------- device scratch ----------------
__device__ float g_S2[G][NCH][NCH];
__device__ float g_sum[G][NCH];
__device__ float g_wm[G][NCH][NCH];   // [g][c][d], weight+sqrt(rTr) folded in
__device__ float g_beta[G][NCH];

// ---------------- helpers ----------------
__device__ __forceinline__ uint32_t tf32r(float f) {
    uint32_t r; asm("cvt.rn.tf32.f32 %0, %1;" : "=r"(r) : "f"(f)); return r;
}
// D += A(16x8 tf32) * B(8x8 tf32), fp32 accum
__device__ __forceinline__ void mma8(float* d, const uint32_t* a,
                                     uint32_t b0, uint32_t b1) {
    asm volatile("mma.sync.aligned.m16n8k8.row.col.f32.tf32.tf32.f32 "
                 "{%0,%1,%2,%3}, {%4,%5,%6,%7}, {%8,%9}, {%0,%1,%2,%3};"
                 : "+f"(d[0]), "+f"(d[1]), "+f"(d[2]), "+f"(d[3])
                 : "r"(a[0]), "r"(a[1]), "r"(a[2]), "r"(a[3]),
                   "r"(b0), "r"(b1));
}

// ---------------- zero scratch ----------------
__global__ void zero_kernel() {
    int i = blockIdx.x * blockDim.x + threadIdx.x;
    if (i < G * NCH * NCH) (&g_S2[0][0][0])[i] = 0.0f;
    if (i < G * NCH)       (&g_sum[0][0])[i]   = 0.0f;
}

// ---------------- phase 1: covariance via HMMA tf32 ----------------
// S2 += X X^T over this block's tiles. Per warp: 16x32 strip of the 64x64
// output, fp32 accumulators held across all tiles, one atomic flush.
__global__ __launch_bounds__(256, 2) void cov_kernel(const float* __restrict__ x) {
    __shared__ uint32_t st[NCH][SPAD];   // tf32 bits, [channel][sample]

    const int gi  = blockIdx.x / NBLK;
    const int blk = blockIdx.x % NBLK;
    const int tid = threadIdx.x;
    const int w   = tid >> 5, lane = tid & 31;
    const int g   = lane >> 2, t4 = lane & 3;
    const int rs  = w >> 1, cs = w & 1;           // 16-row strip, 32-col strip
    const int r0  = rs * 16 + g;

    // tile-load mapping: 4 float4 per thread
    const int lc = tid >> 4;           // channels lc, lc+16, lc+32, lc+48
    const int ls = (tid & 15) * 4;     // sample offset

    const float* xg = x + (size_t)gi * NCH * HWX;

    float acc[16];                     // 4 col-blocks x 4 regs
    #pragma unroll
    for (int i = 0; i < 16; i++) acc[i] = 0.0f;
    float sacc[4] = {0.f, 0.f, 0.f, 0.f};

    // prologue prefetch
    float4 pf[4];
    {
        const int b = blk / CHUNKS, so = (blk % CHUNKS) * TSAMP;
        const float* base = xg + (size_t)b * CC * HWX + so + ls;
        #pragma unroll
        for (int i = 0; i < 4; i++)
            pf[i] = *(const float4*)(base + (size_t)(lc + 16 * i) * HWX);
    }

    for (int t = blk; t < TILESG; t += NBLK) {
        __syncthreads();               // previous tile fully consumed
        #pragma unroll
        for (int i = 0; i < 4; i++) {
            const int c = lc + 16 * i;
            st[c][ls + 0] = tf32r(pf[i].x);
            st[c][ls + 1] = tf32r(pf[i].y);
            st[c][ls + 2] = tf32r(pf[i].z);
            st[c][ls + 3] = tf32r(pf[i].w);
            sacc[i] += (pf[i].x + pf[i].y) + (pf[i].z + pf[i].w);
        }
        __syncthreads();               // tile ready

        const int tn = t + NBLK;
        if (tn < TILESG) {             // overlap next load with compute
            const int b = tn / CHUNKS, so = (tn % CHUNKS) * TSAMP;
            const float* base = xg + (size_t)b * CC * HWX + so + ls;
            #pragma unroll
            for (int i = 0; i < 4; i++)
                pf[i] = *(const float4*)(base + (size_t)(lc + 16 * i) * HWX);
        }

        #pragma unroll
        for (int kk = 0; kk < 8; kk++) {
            const int k0 = kk * 8;
            uint32_t a[4];
            a[0] = st[r0][k0 + t4];
            a[1] = st[r0 + 8][k0 + t4];
            a[2] = st[r0][k0 + t4 + 4];
            a[3] = st[r0 + 8][k0 + t4 + 4];
            #pragma unroll
            for (int j = 0; j < 4; j++) {
                const int n0 = cs * 32 + j * 8 + g;
                mma8(&acc[j * 4], a, st[n0][k0 + t4], st[n0][k0 + t4 + 4]);
            }
        }
    }

    // flush S2 strip
    #pragma unroll
    for (int j = 0; j < 4; j++) {
        const int c0 = cs * 32 + j * 8 + 2 * t4;
        atomicAdd(&g_S2[gi][r0][c0],     acc[j * 4 + 0]);
        atomicAdd(&g_S2[gi][r0][c0 + 1], acc[j * 4 + 1]);
        atomicAdd(&g_S2[gi][r0 + 8][c0],     acc[j * 4 + 2]);
        atomicAdd(&g_S2[gi][r0 + 8][c0 + 1], acc[j * 4 + 3]);
    }
    // channel sums: 16 threads (same tid>>4) share each channel set
    #pragma unroll
    for (int i = 0; i < 4; i++) {
        float v = sacc[i];
        v += __shfl_down_sync(0xffffffffu, v, 8, 16);
        v += __shfl_down_sync(0xffffffffu, v, 4, 16);
        v += __shfl_down_sync(0xffffffffu, v, 2, 16);
        v += __shfl_down_sync(0xffffffffu, v, 1, 16);
        if ((tid & 15) == 0) atomicAdd(&g_sum[gi][lc + 16 * i], v);
    }
}

// ---------------- phase 2: Newton-Schulz + folding (proven R2 version) -----
__device__ __forceinline__ void mm64(float* O, const float* A, const float* B) {
    const int r = threadIdx.x >> 2, cb = (threadIdx.x & 3) << 4;
    float acc[16] = {};
    for (int k = 0; k < 64; k++) {
        float a = A[r * 65 + k];
        #pragma unroll
        for (int j = 0; j < 16; j++) acc[j] += a * B[k * 65 + cb + j];
    }
    #pragma unroll
    for (int j = 0; j < 16; j++) O[r * 65 + cb + j] = acc[j];
    __syncthreads();
}

__global__ __launch_bounds__(256) void ns_kernel(const float* __restrict__ weight,
                                                 const float* __restrict__ bias) {
    extern __shared__ float sm[];
    float* Sn = sm;        float* Pm = sm + 4160;
    float* T1 = sm + 8320; float* T2 = sm + 12480;
    float* mean = sm + 16640; float* misc = sm + 16704;
    const int gi = blockIdx.x, tid = threadIdx.x;
    const int r = tid >> 2, cb = (tid & 3) << 4;

    if (tid < 64) mean[tid] = g_sum[gi][tid] * (1.0f / MTOT);
    __syncthreads();
    #pragma unroll
    for (int j = 0; j < 16; j++) {
        int c = cb + j;
        float sig = g_S2[gi][r][c] * (1.0f / MTOT) - mean[r] * mean[c];
        if (r == c) sig += EPSV;
        Sn[r * 65 + c] = sig;
    }
    __syncthreads();
    if (tid < 32) {
        float ts = Sn[tid * 65 + tid] + Sn[(tid + 32) * 65 + (tid + 32)];
        #pragma unroll
        for (int o = 16; o; o >>= 1) ts += __shfl_xor_sync(0xffffffffu, ts, o);
        if (tid == 0) misc[0] = 1.0f / ts;
    }
    __syncthreads();
    const float rTr = misc[0];
    #pragma unroll
    for (int j = 0; j < 16; j++) {
        int c = cb + j;
        Sn[r * 65 + c] *= rTr;
        Pm[r * 65 + c] = (r == c) ? 1.0f : 0.0f;
    }
    __syncthreads();
    for (int it = 0; it < NS_T; it++) {
        mm64(T1, Pm, Pm); mm64(T2, T1, Pm); mm64(T1, T2, Sn);
        #pragma unroll
        for (int j = 0; j < 16; j++) {
            int idx = r * 65 + cb + j;
            Pm[idx] = 1.5f * Pm[idx] - 0.5f * T1[idx];
        }
        __syncthreads();
    }
    const float s = sqrtf(rTr);
    #pragma unroll
    for (int j = 0; j < 16; j++) {
        int d = cb + j;
        g_wm[gi][r][d] = Pm[r * 65 + d] * s * weight[gi * NCH + r];
    }
    if (tid < 64) {
        float off = 0.0f;
        for (int d = 0; d < 64; d++) off += Pm[tid * 65 + d] * mean[d];
        g_beta[gi][tid] = bias[gi * NCH + tid] - weight[gi * NCH + tid] * s * off;
    }
}

// ---------------- phase 3: whitening apply via HMMA tf32 ----------------
// out[c][s] = sum_d wm[c][d] * x[d][s] + beta[c]. wm A-fragments live in
// registers for the whole kernel; x tiles staged via the same pipeline.
__global__ __launch_bounds__(256, 2) void whiten_kernel(const float* __restrict__ x,
                                                        float* __restrict__ out) {
    __shared__ uint32_t st[NCH][SPAD];   // tf32 bits, [channel(k)][sample(n)]

    const int gi  = blockIdx.x / NBLK;
    const int blk = blockIdx.x % NBLK;
    const int tid = threadIdx.x;
    const int w   = tid >> 5, lane = tid & 31;
    const int g   = lane >> 2, t4 = lane & 3;
    const int rs  = w >> 1, cs = w & 1;
    const int r0  = rs * 16 + g;

    const int lc = tid >> 4;
    const int ls = (tid & 15) * 4;

    // hoist wm A-fragments (row-major 16x64 strip) into registers
    uint32_t afr[8][4];
    #pragma unroll
    for (int kk = 0; kk < 8; kk++) {
        const int k0 = kk * 8;
        afr[kk][0] = tf32r(g_wm[gi][r0][k0 + t4]);
        afr[kk][1] = tf32r(g_wm[gi][r0 + 8][k0 + t4]);
        afr[kk][2] = tf32r(g_wm[gi][r0][k0 + t4 + 4]);
        afr[kk][3] = tf32r(g_wm[gi][r0 + 8][k0 + t4 + 4]);
    }
    const float bet0 = g_beta[gi][r0];
    const float bet1 = g_beta[gi][r0 + 8];

    const float* xg = x + (size_t)gi * NCH * HWX;
    float* og = out + (size_t)gi * NCH * HWX;

    float4 pf[4];
    {
        const int b = blk / CHUNKS, so = (blk % CHUNKS) * TSAMP;
        const float* base = xg + (size_t)b * CC * HWX + so + ls;
        #pragma unroll
        for (int i = 0; i < 4; i++)
            pf[i] = *(const float4*)(base + (size_t)(lc + 16 * i) * HWX);
    }

    for (int t = blk; t < TILESG; t += NBLK) {
        __syncthreads();
        #pragma unroll
        for (int i = 0; i < 4; i++) {
            const int c = lc + 16 * i;
            st[c][ls + 0] = tf32r(pf[i].x);
            st[c][ls + 1] = tf32r(pf[i].y);
            st[c][ls + 2] = tf32r(pf[i].z);
            st[c][ls + 3] = tf32r(pf[i].w);
        }
        __syncthreads();

        const int tn = t + NBLK;
        if (tn < TILESG) {
            const int b = tn / CHUNKS, so = (tn % CHUNKS) * TSAMP;
            const float* base = xg + (size_t)b * CC * HWX + so + ls;
            #pragma unroll
            for (int i = 0; i < 4; i++)
                pf[i] = *(const float4*)(base + (size_t)(lc + 16 * i) * HWX);
        }

        float acc[16];
        #pragma unroll
        for (int i = 0; i < 16; i++) acc[i] = 0.0f;

        #pragma unroll
        for (int kk = 0; kk < 8; kk++) {
            const int k0 = kk * 8;
            #pragma unroll
            for (int j = 0; j < 4; j++) {
                const int n0 = cs * 32 + j * 8 + g;
                mma8(&acc[j * 4], afr[kk],
                     st[k0 + t4][n0], st[k0 + t4 + 4][n0]);
            }
        }

        // epilogue: D + beta -> global (float2 stores)
        const int b = t / CHUNKS, so = (t % CHUNKS) * TSAMP;
        float* ob0 = og + ((size_t)b * CC + r0) * HWX + so;
        float* ob1 = ob0 + (size_t)8 * HWX;
        #pragma unroll
        for (int j = 0; j < 4; j++) {
            const int c0 = cs * 32 + j * 8 + 2 * t4;
            float2 v0 = make_float2(acc[j * 4 + 0] + bet0, acc[j * 4 + 1] + bet0);
            float2 v1 = make_float2(acc[j * 4 + 2] + bet1, acc[j * 4 + 3] + bet1);
            *(float2*)(ob0 + c0) = v0;
            *(float2*)(ob1 + c0) = v1;
        }
    }
}

// ---------------- launch ----------------
extern "C" void kernel_launch(void* const* d_in, const int* in_sizes, int n_in,
                              void* d_out, int out_size) {
    const float* x      = (const float*)d_in[0];
    const float* weight = (const float*)d_in[1];
    const float* bias   = (const float*)d_in[2];
    float* out          = (float*)d_out;

    const int NS_SMEM = (16704 + 16) * 4;
    cudaFuncSetAttribute(ns_kernel, cudaFuncAttributeMaxDynamicSharedMemorySize,
                         NS_SMEM);

    zero_kernel<<<(G * NCH * NCH + 255) / 256, 256>>>();
    cov_kernel<<<G * NBLK, 256>>>(x);
    ns_kernel<<<G, 256, NS_SMEM>>>(weight, bias);
    whiten_kernel<<<G * NBLK, 256>>>(x, out);
}

// round 8
// speedup vs baseline: 2.2127x; 1.0478x over previous
#include <cuda_runtime.h>
#include <cstdint>

// ---------------- problem constants ----------------
#define BB      64
#define CC      256
#define HWX     3136        // 56*56
#define G       4
#define NCH     64
#define MTOT    (BB*HWX)
#define NBLK    74          // blocks per group (grid 296 = 2/SM)
#define EPSV    1e-5f
#define NS_T    5

// cov tiling: 64-sample tiles, 3-stage cp.async pipeline
#define CT      64
#define CCHUNK  (HWX/CT)     // 49
#define CTILES  (BB*CCHUNK)  // 3136 per group
#define CP      72           // pitch: 72%32=8 -> conflict-free; 288B row, 16B-mult

// whiten tiling: 128-sample tiles (24 full + 1 half per image), 2-stage
#define WT      128
#define WTPB    25
#define WTILES  (BB*WTPB)    // 1600 per group
#define WP      136          // pitch: 136%32=8; 544B row, 16B-mult

// ---------------- device scratch ----------------
__device__ float g_S2[G][NCH][NCH];
__device__ float g_sum[G][NCH];
__device__ float g_wm[G][NCH][NCH];   // [g][c][d], weight+sqrt(rTr) folded in
__device__ float g_beta[G][NCH];

// ---------------- helpers ----------------
__device__ __forceinline__ uint32_t tf32r(float f) {
    uint32_t r; asm("cvt.rn.tf32.f32 %0, %1;" : "=r"(r) : "f"(f)); return r;
}
__device__ __forceinline__ uint32_t smem_u32(const void* p) {
    uint32_t a;
    asm("{ .reg .u64 t; cvta.to.shared.u64 t, %1; cvt.u32.u64 %0, t; }"
        : "=r"(a) : "l"(p));
    return a;
}
__device__ __forceinline__ void mma8(float* d, const uint32_t* a,
                                     uint32_t b0, uint32_t b1) {
    asm volatile("mma.sync.aligned.m16n8k8.row.col.f32.tf32.tf32.f32 "
                 "{%0,%1,%2,%3}, {%4,%5,%6,%7}, {%8,%9}, {%0,%1,%2,%3};"
                 : "+f"(d[0]), "+f"(d[1]), "+f"(d[2]), "+f"(d[3])
                 : "r"(a[0]), "r"(a[1]), "r"(a[2]), "r"(a[3]),
                   "r"(b0), "r"(b1));
}
#define CP_ASYNC(dst, src) \
    asm volatile("cp.async.cg.shared.global [%0], [%1], 16;" \
                 :: "r"(dst), "l"(src) : "memory")
#define CP_COMMIT() asm volatile("cp.async.commit_group;" ::: "memory")
#define CP_WAIT1()  asm volatile("cp.async.wait_group 1;" ::: "memory")

// ---------------- zero scratch ----------------
__global__ void zero_kernel() {
    int i = blockIdx.x * blockDim.x + threadIdx.x;
    if (i < G * NCH * NCH) (&g_S2[0][0][0])[i] = 0.0f;
    if (i < G * NCH)       (&g_sum[0][0])[i]   = 0.0f;
}

// ---------------- phase 1: covariance (HMMA tf32, cp.async 3-stage) --------
// 8 warps = 4 output quadrants (32x32) x 2 sample-halves (k-split; the
// atomic flush absorbs the k reduction).
__global__ __launch_bounds__(256, 2) void cov_kernel(const float* __restrict__ x) {
    extern __shared__ float smf[];
    const int gi  = blockIdx.x / NBLK;
    const int blk = blockIdx.x % NBLK;
    const int tid = threadIdx.x, w = tid >> 5, lane = tid & 31;
    const int g = lane >> 2, t4 = lane & 3;
    const int rs = (w & 3) >> 1, csb = w & 1, kh = w >> 2;
    const int r0 = rs * 32, c0 = csb * 32;
    const int lc = tid >> 4, ls = (tid & 15) * 4;    // copy map
    const uint32_t sb = smem_u32(smf);
    const float* xg = x + (size_t)gi * NCH * HWX;
    const int ntile = (CTILES - blk + NBLK - 1) / NBLK;

    auto issue = [&](int idx, int buf) {
        if (idx < ntile) {
            const int t = blk + idx * NBLK;
            const int b = t / CCHUNK, so = (t % CCHUNK) * CT;
            const uint32_t dst0 = sb + (uint32_t)(buf * NCH * CP + lc * CP + ls) * 4;
            #pragma unroll
            for (int i = 0; i < 4; i++) {
                const float* src = xg + (size_t)(b * CC + lc + 16 * i) * HWX + so + ls;
                CP_ASYNC(dst0 + (uint32_t)(16 * i * CP) * 4, src);
            }
        }
        CP_COMMIT();
    };

    float acc[32];
    #pragma unroll
    for (int i = 0; i < 32; i++) acc[i] = 0.0f;
    float sch = 0.0f;                       // channel (tid>>2) partial sum

    issue(0, 0); issue(1, 1);
    int buf = 0;
    for (int it = 0; it < ntile; ++it) {
        CP_WAIT1();
        __syncthreads();
        issue(it + 2, (buf + 2) % 3);

        const float* tb = smf + buf * NCH * CP;
        // channel sums from raw fp32 tile
        {
            const float4* sp = (const float4*)(tb + (tid >> 2) * CP + (tid & 3) * 16);
            float4 v0 = sp[0], v1 = sp[1], v2 = sp[2], v3 = sp[3];
            sch += (((v0.x + v0.y) + (v0.z + v0.w)) + ((v1.x + v1.y) + (v1.z + v1.w)))
                 + (((v2.x + v2.y) + (v2.z + v2.w)) + ((v3.x + v3.y) + (v3.z + v3.w)));
        }
        const uint32_t* tu = (const uint32_t*)tb;
        #pragma unroll
        for (int kk2 = 0; kk2 < 4; kk2++) {
            const int k0 = (kh * 4 + kk2) * 8;
            uint32_t a0[4], a1[4];
            a0[0] = tu[(r0 + g) * CP + k0 + t4];
            a0[1] = tu[(r0 + g + 8) * CP + k0 + t4];
            a0[2] = tu[(r0 + g) * CP + k0 + t4 + 4];
            a0[3] = tu[(r0 + g + 8) * CP + k0 + t4 + 4];
            a1[0] = tu[(r0 + 16 + g) * CP + k0 + t4];
            a1[1] = tu[(r0 + 24 + g) * CP + k0 + t4];
            a1[2] = tu[(r0 + 16 + g) * CP + k0 + t4 + 4];
            a1[3] = tu[(r0 + 24 + g) * CP + k0 + t4 + 4];
            #pragma unroll
            for (int j = 0; j < 4; j++) {
                const int n0 = c0 + j * 8 + g;
                const uint32_t b0 = tu[n0 * CP + k0 + t4];
                const uint32_t b1 = tu[n0 * CP + k0 + t4 + 4];
                mma8(acc + j * 4,      a0, b0, b1);
                mma8(acc + 16 + j * 4, a1, b0, b1);
            }
        }
        buf = (buf + 1) % 3;
    }

    // flush
    #pragma unroll
    for (int mh = 0; mh < 2; mh++) {
        const int R = r0 + mh * 16;
        #pragma unroll
        for (int j = 0; j < 4; j++) {
            const int cc0 = c0 + j * 8 + 2 * t4;
            atomicAdd(&g_S2[gi][R + g][cc0],     acc[mh * 16 + j * 4 + 0]);
            atomicAdd(&g_S2[gi][R + g][cc0 + 1], acc[mh * 16 + j * 4 + 1]);
            atomicAdd(&g_S2[gi][R + g + 8][cc0],     acc[mh * 16 + j * 4 + 2]);
            atomicAdd(&g_S2[gi][R + g + 8][cc0 + 1], acc[mh * 16 + j * 4 + 3]);
        }
    }
    float v = sch;
    v += __shfl_down_sync(0xffffffffu, v, 2, 4);
    v += __shfl_down_sync(0xffffffffu, v, 1, 4);
    if ((tid & 3) == 0) atomicAdd(&g_sum[gi][tid >> 2], v);
}

// ---------------- phase 2: Newton-Schulz + folding ----------------
__device__ __forceinline__ void mm64(float* O, const float* A, const float* B) {
    const int r = threadIdx.x >> 2, cb = (threadIdx.x & 3) << 4;
    float acc[16] = {};
    for (int k = 0; k < 64; k++) {
        const float a = A[r * 68 + k];
        const float4* bp = (const float4*)(B + k * 68 + cb);
        float4 b0 = bp[0], b1 = bp[1], b2 = bp[2], b3 = bp[3];
        acc[0]  += a * b0.x; acc[1]  += a * b0.y; acc[2]  += a * b0.z; acc[3]  += a * b0.w;
        acc[4]  += a * b1.x; acc[5]  += a * b1.y; acc[6]  += a * b1.z; acc[7]  += a * b1.w;
        acc[8]  += a * b2.x; acc[9]  += a * b2.y; acc[10] += a * b2.z; acc[11] += a * b2.w;
        acc[12] += a * b3.x; acc[13] += a * b3.y; acc[14] += a * b3.z; acc[15] += a * b3.w;
    }
    #pragma unroll
    for (int j = 0; j < 16; j++) O[r * 68 + cb + j] = acc[j];
    __syncthreads();
}

__global__ __launch_bounds__(256) void ns_kernel(const float* __restrict__ weight,
                                                 const float* __restrict__ bias) {
    extern __shared__ float sm[];
    float* Sn = sm;         float* Pm = sm + 4352;
    float* T1 = sm + 8704;  float* T2 = sm + 13056;
    float* mean = sm + 17408; float* misc = sm + 17472;
    const int gi = blockIdx.x, tid = threadIdx.x;
    const int r = tid >> 2, cb = (tid & 3) << 4;

    if (tid < 64) mean[tid] = g_sum[gi][tid] * (1.0f / MTOT);
    __syncthreads();
    #pragma unroll
    for (int j = 0; j < 16; j++) {
        int c = cb + j;
        float sig = g_S2[gi][r][c] * (1.0f / MTOT) - mean[r] * mean[c];
        if (r == c) sig += EPSV;
        Sn[r * 68 + c] = sig;
    }
    __syncthreads();
    if (tid < 32) {
        float ts = Sn[tid * 68 + tid] + Sn[(tid + 32) * 68 + (tid + 32)];
        #pragma unroll
        for (int o = 16; o; o >>= 1) ts += __shfl_xor_sync(0xffffffffu, ts, o);
        if (tid == 0) misc[0] = 1.0f / ts;
    }
    __syncthreads();
    const float rTr = misc[0];
    #pragma unroll
    for (int j = 0; j < 16; j++) {
        int c = cb + j;
        Sn[r * 68 + c] *= rTr;
        Pm[r * 68 + c] = (r == c) ? 1.0f : 0.0f;
    }
    __syncthreads();
    for (int it = 0; it < NS_T; it++) {
        mm64(T1, Pm, Pm); mm64(T2, T1, Pm); mm64(T1, T2, Sn);
        #pragma unroll
        for (int j = 0; j < 16; j++) {
            int idx = r * 68 + cb + j;
            Pm[idx] = 1.5f * Pm[idx] - 0.5f * T1[idx];
        }
        __syncthreads();
    }
    const float s = sqrtf(rTr);
    #pragma unroll
    for (int j = 0; j < 16; j++) {
        int d = cb + j;
        g_wm[gi][r][d] = Pm[r * 68 + d] * s * weight[gi * NCH + r];
    }
    if (tid < 64) {
        float off = 0.0f;
        for (int d = 0; d < 64; d++) off += Pm[tid * 68 + d] * mean[d];
        g_beta[gi][tid] = bias[gi * NCH + tid] - weight[gi * NCH + tid] * s * off;
    }
}

// ---------------- phase 3: whitening apply (HMMA tf32, cp.async 2-stage) ---
// 8 warps: 2 row-strips (32ch) x 4 sample-strips (32) over 64x128 tiles.
// wm A-fragments live in registers; B-LDS per output halved vs 16x32 tiling.
__global__ __launch_bounds__(256, 2) void whiten_kernel(const float* __restrict__ x,
                                                        float* __restrict__ out) {
    extern __shared__ float smf[];
    const int gi  = blockIdx.x / NBLK;
    const int blk = blockIdx.x % NBLK;
    const int tid = threadIdx.x, w = tid >> 5, lane = tid & 31;
    const int g = lane >> 2, t4 = lane & 3;
    const int rs = w & 1, nt = w >> 1;
    const int lc = tid >> 5, s4 = (tid & 31) * 4;    // copy map
    const uint32_t sb = smem_u32(smf);
    const float* xg = x + (size_t)gi * NCH * HWX;
    float* og = out + (size_t)gi * NCH * HWX;
    const int ntile = (WTILES - blk + NBLK - 1) / NBLK;

    // hoist wm A-fragments + beta
    uint32_t afr[8][2][4];
    float bet[2][2];
    #pragma unroll
    for (int kk = 0; kk < 8; kk++) {
        const int k0 = kk * 8;
        #pragma unroll
        for (int mh = 0; mh < 2; mh++) {
            const int R = rs * 32 + mh * 16;
            afr[kk][mh][0] = tf32r(g_wm[gi][R + g][k0 + t4]);
            afr[kk][mh][1] = tf32r(g_wm[gi][R + g + 8][k0 + t4]);
            afr[kk][mh][2] = tf32r(g_wm[gi][R + g][k0 + t4 + 4]);
            afr[kk][mh][3] = tf32r(g_wm[gi][R + g + 8][k0 + t4 + 4]);
        }
    }
    #pragma unroll
    for (int mh = 0; mh < 2; mh++) {
        bet[mh][0] = g_beta[gi][rs * 32 + mh * 16 + g];
        bet[mh][1] = g_beta[gi][rs * 32 + mh * 16 + g + 8];
    }

    auto issue = [&](int idx) {
        if (idx < ntile) {
            const int t = blk + idx * NBLK;
            const int b = t / WTPB, rem = t % WTPB;
            const int hw0 = rem * WT;
            const bool half = (rem == WTPB - 1);
            if (!half || (tid & 31) < 16) {
                const uint32_t dst0 = sb + (uint32_t)((idx & 1) * NCH * WP + lc * WP + s4) * 4;
                #pragma unroll
                for (int i = 0; i < 8; i++) {
                    const float* src = xg + (size_t)(b * CC + lc + 8 * i) * HWX + hw0 + s4;
                    CP_ASYNC(dst0 + (uint32_t)(8 * i * WP) * 4, src);
                }
            }
        }
        CP_COMMIT();
    };

    issue(0);
    for (int it = 0; it < ntile; ++it) {
        __syncthreads();           // all warps done with buf (it+1)&1 (tile it-1)
        issue(it + 1);
        CP_WAIT1();                // tile it arrived
        __syncthreads();

        const int t = blk + it * NBLK;
        const int b = t / WTPB, rem = t % WTPB;
        const int hw0 = rem * WT;
        const bool half = (rem == WTPB - 1);
        if (!(half && nt >= 2)) {
            const uint32_t* tu = (const uint32_t*)(smf + (it & 1) * NCH * WP);
            float acc[32];
            #pragma unroll
            for (int i = 0; i < 32; i++) acc[i] = 0.0f;
            #pragma unroll
            for (int kk = 0; kk < 8; kk++) {
                const int k0 = kk * 8;
                #pragma unroll
                for (int j = 0; j < 4; j++) {
                    const int n0 = nt * 32 + j * 8 + g;
                    const uint32_t b0 = tu[(k0 + t4) * WP + n0];
                    const uint32_t b1 = tu[(k0 + t4 + 4) * WP + n0];
                    mma8(acc + j * 4,      afr[kk][0], b0, b1);
                    mma8(acc + 16 + j * 4, afr[kk][1], b0, b1);
                }
            }
            #pragma unroll
            for (int mh = 0; mh < 2; mh++) {
                #pragma unroll
                for (int j = 0; j < 4; j++) {
                    const int row = rs * 32 + mh * 16 + g;
                    const int col = nt * 32 + j * 8 + 2 * t4;
                    float* o0 = og + ((size_t)b * CC + row) * HWX + hw0 + col;
                    float2 v0 = make_float2(acc[mh * 16 + j * 4 + 0] + bet[mh][0],
                                            acc[mh * 16 + j * 4 + 1] + bet[mh][0]);
                    float2 v1 = make_float2(acc[mh * 16 + j * 4 + 2] + bet[mh][1],
                                            acc[mh * 16 + j * 4 + 3] + bet[mh][1]);
                    *(float2*)o0 = v0;
                    *(float2*)(o0 + (size_t)8 * HWX) = v1;
                }
            }
        }
    }
}

// ---------------- launch ----------------
extern "C" void kernel_launch(void* const* d_in, const int* in_sizes, int n_in,
                              void* d_out, int out_size) {
    const float* x      = (const float*)d_in[0];
    const float* weight = (const float*)d_in[1];
    const float* bias   = (const float*)d_in[2];
    float* out          = (float*)d_out;

    const int NS_SMEM  = (17472 + 16) * 4;        // 69952
    const int COV_SMEM = 3 * NCH * CP * 4;        // 55296
    const int WHT_SMEM = 2 * NCH * WP * 4;        // 69632
    cudaFuncSetAttribute(ns_kernel,     cudaFuncAttributeMaxDynamicSharedMemorySize, NS_SMEM);
    cudaFuncSetAttribute(cov_kernel,    cudaFuncAttributeMaxDynamicSharedMemorySize, COV_SMEM);
    cudaFuncSetAttribute(whiten_kernel, cudaFuncAttributeMaxDynamicSharedMemorySize, WHT_SMEM);

    zero_kernel<<<(G * NCH * NCH + 255) / 256, 256>>>();
    cov_kernel<<<G * NBLK, 256, COV_SMEM>>>(x);
    ns_kernel<<<G, 256, NS_SMEM>>>(weight, bias);
    whiten_kernel<<<G * NBLK, 256, WHT_SMEM>>>(x, out);
}

// round 9
// speedup vs baseline: 2.3691x; 1.0707x over previous
#include <cuda_runtime.h>
#include <cstdint>

// ---------------- problem constants ----------------
#define BB      64
#define CC      256
#define HWX     3136        // 56*56
#define G       4
#define NCH     64
#define MTOT    (BB*HWX)
#define NBLK    74          // blocks per group (grid 296 = 2/SM)
#define EPSV    1e-5f
#define NS_T    5

// cov tiling: 64-sample tiles, 3-stage cp.async pipeline
#define CT      64
#define CCHUNK  (HWX/CT)     // 49
#define CTILES  (BB*CCHUNK)  // 3136 per group
#define CP      68           // pitch%32==4 -> conflict-free frag loads; 272B row

// whiten tiling: 128-sample tiles (24 full + 1 half per image), 2-stage
#define WT      128
#define WTPB    25
#define WTILES  (BB*WTPB)    // 1600 per group
#define WP      136          // pitch%32==8 -> conflict-free B reads

// ---------------- device scratch ----------------
__device__ float g_S2[G][NCH][NCH];
__device__ float g_sum[G][NCH];
__device__ float g_wm[G][NCH][NCH];   // [g][c][d], weight+sqrt(rTr) folded in
__device__ float g_beta[G][NCH];

// ---------------- helpers ----------------
__device__ __forceinline__ uint32_t tf32r(float f) {
    uint32_t r; asm("cvt.rn.tf32.f32 %0, %1;" : "=r"(r) : "f"(f)); return r;
}
__device__ __forceinline__ uint32_t smem_u32(const void* p) {
    uint32_t a;
    asm("{ .reg .u64 t; cvta.to.shared.u64 t, %1; cvt.u32.u64 %0, t; }"
        : "=r"(a) : "l"(p));
    return a;
}
__device__ __forceinline__ void mma8(float* d, const uint32_t* a,
                                     uint32_t b0, uint32_t b1) {
    asm volatile("mma.sync.aligned.m16n8k8.row.col.f32.tf32.tf32.f32 "
                 "{%0,%1,%2,%3}, {%4,%5,%6,%7}, {%8,%9}, {%0,%1,%2,%3};"
                 : "+f"(d[0]), "+f"(d[1]), "+f"(d[2]), "+f"(d[3])
                 : "r"(a[0]), "r"(a[1]), "r"(a[2]), "r"(a[3]),
                   "r"(b0), "r"(b1));
}
#define CP_ASYNC(dst, src) \
    asm volatile("cp.async.cg.shared.global [%0], [%1], 16;" \
                 :: "r"(dst), "l"(src) : "memory")
#define CP_COMMIT() asm volatile("cp.async.commit_group;" ::: "memory")
#define CP_WAIT1()  asm volatile("cp.async.wait_group 1;" ::: "memory")
#define CP_WAIT2()  asm volatile("cp.async.wait_group 2;" ::: "memory")

// ---------------- zero scratch ----------------
__global__ void zero_kernel() {
    int i = blockIdx.x * blockDim.x + threadIdx.x;
    if (i < G * NCH * NCH) (&g_S2[0][0][0])[i] = 0.0f;
    if (i < G * NCH)       (&g_sum[0][0])[i]   = 0.0f;
}

// ---------------- phase 1: covariance (HMMA tf32, symmetric, 3-stage) ------
// Upper-triangle quadrants only: warps 0,1 -> q(0,0) k-halves; warps 2-5 ->
// q(0,32) k-quarters (+ channel-sum duty); warps 6,7 -> q(32,32) k-halves.
// ns_kernel symmetrizes the missing lower-left quadrant.
__global__ __launch_bounds__(256, 2) void cov_kernel(const float* __restrict__ x) {
    extern __shared__ float smf[];
    const int gi  = blockIdx.x / NBLK;
    const int blk = blockIdx.x % NBLK;
    const int tid = threadIdx.x, w = tid >> 5, lane = tid & 31;
    const int g = lane >> 2, t4 = lane & 3;

    int r0, c0, kbase, nkk;
    if (w < 2)      { r0 = 0;  c0 = 0;  kbase = (w & 1) * 4; nkk = 4; }
    else if (w < 6) { r0 = 0;  c0 = 32; kbase = (w - 2) * 2; nkk = 2; }
    else            { r0 = 32; c0 = 32; kbase = (w & 1) * 4; nkk = 4; }
    const bool sumduty = (w >= 2) && (w < 6);
    const int sch_ch   = (tid - 64) >> 1;     // 0..63 (valid when sumduty)
    const int sch_half = tid & 1;

    const int lc = tid >> 4, ls = (tid & 15) * 4;    // copy map
    const uint32_t sb = smem_u32(smf);
    const float* xg = x + (size_t)gi * NCH * HWX;
    const int ntile = (CTILES - blk + NBLK - 1) / NBLK;

    auto issue = [&](int idx, int buf) {
        if (idx < ntile) {
            const int t = blk + idx * NBLK;
            const int b = t / CCHUNK, so = (t % CCHUNK) * CT;
            const uint32_t dst0 = sb + (uint32_t)(buf * NCH * CP + lc * CP + ls) * 4;
            #pragma unroll
            for (int i = 0; i < 4; i++) {
                const float* src = xg + (size_t)(b * CC + lc + 16 * i) * HWX + so + ls;
                CP_ASYNC(dst0 + (uint32_t)(16 * i * CP) * 4, src);
            }
        }
        CP_COMMIT();
    };

    float acc[32];
    #pragma unroll
    for (int i = 0; i < 32; i++) acc[i] = 0.0f;
    float sch = 0.0f;

    issue(0, 0); issue(1, 1);
    for (int it = 0; it < ntile; ++it) {
        __syncthreads();                    // compute(it-1) done everywhere
        issue(it + 2, (it + 2) % 3);        // overwrite buffer consumed at it-1
        CP_WAIT2();                         // tile it landed (it+1, it+2 in flight)
        __syncthreads();

        const float* tb = smf + (it % 3) * NCH * CP;
        if (sumduty) {                      // conflict-free rotated-slot reads
            #pragma unroll
            for (int i = 0; i < 8; i++) {
                const int slot = 8 * sch_half + ((i + 4 * sch_half) & 7);
                float4 v = *(const float4*)(tb + sch_ch * CP + slot * 4);
                sch += (v.x + v.y) + (v.z + v.w);
            }
        }
        const uint32_t* tu = (const uint32_t*)tb;
        #pragma unroll
        for (int kk = 0; kk < 4; kk++) {
            if (kk < nkk) {
                const int k0 = (kbase + kk) * 8;
                uint32_t a0[4], a1[4];
                a0[0] = tu[(r0 + g) * CP + k0 + t4];
                a0[1] = tu[(r0 + g + 8) * CP + k0 + t4];
                a0[2] = tu[(r0 + g) * CP + k0 + t4 + 4];
                a0[3] = tu[(r0 + g + 8) * CP + k0 + t4 + 4];
                a1[0] = tu[(r0 + 16 + g) * CP + k0 + t4];
                a1[1] = tu[(r0 + 24 + g) * CP + k0 + t4];
                a1[2] = tu[(r0 + 16 + g) * CP + k0 + t4 + 4];
                a1[3] = tu[(r0 + 24 + g) * CP + k0 + t4 + 4];
                #pragma unroll
                for (int j = 0; j < 4; j++) {
                    const int n0 = c0 + j * 8 + g;
                    const uint32_t b0 = tu[n0 * CP + k0 + t4];
                    const uint32_t b1 = tu[n0 * CP + k0 + t4 + 4];
                    mma8(acc + j * 4,      a0, b0, b1);
                    mma8(acc + 16 + j * 4, a1, b0, b1);
                }
            }
        }
    }

    // flush quadrant
    #pragma unroll
    for (int mh = 0; mh < 2; mh++) {
        const int R = r0 + mh * 16;
        #pragma unroll
        for (int j = 0; j < 4; j++) {
            const int cc0 = c0 + j * 8 + 2 * t4;
            atomicAdd(&g_S2[gi][R + g][cc0],     acc[mh * 16 + j * 4 + 0]);
            atomicAdd(&g_S2[gi][R + g][cc0 + 1], acc[mh * 16 + j * 4 + 1]);
            atomicAdd(&g_S2[gi][R + g + 8][cc0],     acc[mh * 16 + j * 4 + 2]);
            atomicAdd(&g_S2[gi][R + g + 8][cc0 + 1], acc[mh * 16 + j * 4 + 3]);
        }
    }
    if (sumduty) {
        sch += __shfl_xor_sync(0xffffffffu, sch, 1);
        if (sch_half == 0) atomicAdd(&g_sum[gi][sch_ch], sch);
    }
}

// ---------------- phase 2: Newton-Schulz + folding ----------------
__device__ __forceinline__ void mm64(float* O, const float* A, const float* B) {
    const int r = threadIdx.x >> 2, cb = (threadIdx.x & 3) << 4;
    float acc[16] = {};
    for (int k = 0; k < 64; k++) {
        const float a = A[r * 68 + k];
        const float4* bp = (const float4*)(B + k * 68 + cb);
        float4 b0 = bp[0], b1 = bp[1], b2 = bp[2], b3 = bp[3];
        acc[0]  += a * b0.x; acc[1]  += a * b0.y; acc[2]  += a * b0.z; acc[3]  += a * b0.w;
        acc[4]  += a * b1.x; acc[5]  += a * b1.y; acc[6]  += a * b1.z; acc[7]  += a * b1.w;
        acc[8]  += a * b2.x; acc[9]  += a * b2.y; acc[10] += a * b2.z; acc[11] += a * b2.w;
        acc[12] += a * b3.x; acc[13] += a * b3.y; acc[14] += a * b3.z; acc[15] += a * b3.w;
    }
    #pragma unroll
    for (int j = 0; j < 16; j++) O[r * 68 + cb + j] = acc[j];
    __syncthreads();
}

__global__ __launch_bounds__(256) void ns_kernel(const float* __restrict__ weight,
                                                 const float* __restrict__ bias) {
    extern __shared__ float sm[];
    float* Sn = sm;         float* Pm = sm + 4352;
    float* T1 = sm + 8704;  float* T2 = sm + 13056;
    float* mean = sm + 17408; float* misc = sm + 17472;
    const int gi = blockIdx.x, tid = threadIdx.x;
    const int r = tid >> 2, cb = (tid & 3) << 4;

    if (tid < 64) mean[tid] = g_sum[gi][tid] * (1.0f / MTOT);
    __syncthreads();
    #pragma unroll
    for (int j = 0; j < 16; j++) {
        int c = cb + j;
        // cov kernel only fills the upper-triangle quadrants; symmetrize here
        float s2v = (r >= 32 && c < 32) ? g_S2[gi][c][r] : g_S2[gi][r][c];
        float sig = s2v * (1.0f / MTOT) - mean[r] * mean[c];
        if (r == c) sig += EPSV;
        Sn[r * 68 + c] = sig;
    }
    __syncthreads();
    if (tid < 32) {
        float ts = Sn[tid * 68 + tid] + Sn[(tid + 32) * 68 + (tid + 32)];
        #pragma unroll
        for (int o = 16; o; o >>= 1) ts += __shfl_xor_sync(0xffffffffu, ts, o);
        if (tid == 0) misc[0] = 1.0f / ts;
    }
    __syncthreads();
    const float rTr = misc[0];
    #pragma unroll
    for (int j = 0; j < 16; j++) {
        int c = cb + j;
        Sn[r * 68 + c] *= rTr;
        Pm[r * 68 + c] = (r == c) ? 1.0f : 0.0f;
    }
    __syncthreads();
    for (int it = 0; it < NS_T; it++) {
        mm64(T1, Pm, Pm); mm64(T2, T1, Pm); mm64(T1, T2, Sn);
        #pragma unroll
        for (int j = 0; j < 16; j++) {
            int idx = r * 68 + cb + j;
            Pm[idx] = 1.5f * Pm[idx] - 0.5f * T1[idx];
        }
        __syncthreads();
    }
    const float s = sqrtf(rTr);
    #pragma unroll
    for (int j = 0; j < 16; j++) {
        int d = cb + j;
        g_wm[gi][r][d] = Pm[r * 68 + d] * s * weight[gi * NCH + r];
    }
    if (tid < 64) {
        float off = 0.0f;
        for (int d = 0; d < 64; d++) off += Pm[tid * 68 + d] * mean[d];
        g_beta[gi][tid] = bias[gi * NCH + tid] - weight[gi * NCH + tid] * s * off;
    }
}

// ---------------- phase 3: whitening apply (unchanged from R8, 80us) -------
__global__ __launch_bounds__(256, 2) void whiten_kernel(const float* __restrict__ x,
                                                        float* __restrict__ out) {
    extern __shared__ float smf[];
    const int gi  = blockIdx.x / NBLK;
    const int blk = blockIdx.x % NBLK;
    const int tid = threadIdx.x, w = tid >> 5, lane = tid & 31;
    const int g = lane >> 2, t4 = lane & 3;
    const int rs = w & 1, nt = w >> 1;
    const int lc = tid >> 5, s4 = (tid & 31) * 4;
    const uint32_t sb = smem_u32(smf);
    const float* xg = x + (size_t)gi * NCH * HWX;
    float* og = out + (size_t)gi * NCH * HWX;
    const int ntile = (WTILES - blk + NBLK - 1) / NBLK;

    uint32_t afr[8][2][4];
    float bet[2][2];
    #pragma unroll
    for (int kk = 0; kk < 8; kk++) {
        const int k0 = kk * 8;
        #pragma unroll
        for (int mh = 0; mh < 2; mh++) {
            const int R = rs * 32 + mh * 16;
            afr[kk][mh][0] = tf32r(g_wm[gi][R + g][k0 + t4]);
            afr[kk][mh][1] = tf32r(g_wm[gi][R + g + 8][k0 + t4]);
            afr[kk][mh][2] = tf32r(g_wm[gi][R + g][k0 + t4 + 4]);
            afr[kk][mh][3] = tf32r(g_wm[gi][R + g + 8][k0 + t4 + 4]);
        }
    }
    #pragma unroll
    for (int mh = 0; mh < 2; mh++) {
        bet[mh][0] = g_beta[gi][rs * 32 + mh * 16 + g];
        bet[mh][1] = g_beta[gi][rs * 32 + mh * 16 + g + 8];
    }

    auto issue = [&](int idx) {
        if (idx < ntile) {
            const int t = blk + idx * NBLK;
            const int b = t / WTPB, rem = t % WTPB;
            const int hw0 = rem * WT;
            const bool half = (rem == WTPB - 1);
            if (!half || (tid & 31) < 16) {
                const uint32_t dst0 = sb + (uint32_t)((idx & 1) * NCH * WP + lc * WP + s4) * 4;
                #pragma unroll
                for (int i = 0; i < 8; i++) {
                    const float* src = xg + (size_t)(b * CC + lc + 8 * i) * HWX + hw0 + s4;
                    CP_ASYNC(dst0 + (uint32_t)(8 * i * WP) * 4, src);
                }
            }
        }
        CP_COMMIT();
    };

    issue(0);
    for (int it = 0; it < ntile; ++it) {
        __syncthreads();
        issue(it + 1);
        CP_WAIT1();
        __syncthreads();

        const int t = blk + it * NBLK;
        const int b = t / WTPB, rem = t % WTPB;
        const int hw0 = rem * WT;
        const bool half = (rem == WTPB - 1);
        if (!(half && nt >= 2)) {
            const uint32_t* tu = (const uint32_t*)(smf + (it & 1) * NCH * WP);
            float acc[32];
            #pragma unroll
            for (int i = 0; i < 32; i++) acc[i] = 0.0f;
            #pragma unroll
            for (int kk = 0; kk < 8; kk++) {
                const int k0 = kk * 8;
                #pragma unroll
                for (int j = 0; j < 4; j++) {
                    const int n0 = nt * 32 + j * 8 + g;
                    const uint32_t b0 = tu[(k0 + t4) * WP + n0];
                    const uint32_t b1 = tu[(k0 + t4 + 4) * WP + n0];
                    mma8(acc + j * 4,      afr[kk][0], b0, b1);
                    mma8(acc + 16 + j * 4, afr[kk][1], b0, b1);
                }
            }
            #pragma unroll
            for (int mh = 0; mh < 2; mh++) {
                #pragma unroll
                for (int j = 0; j < 4; j++) {
                    const int row = rs * 32 + mh * 16 + g;
                    const int col = nt * 32 + j * 8 + 2 * t4;
                    float* o0 = og + ((size_t)b * CC + row) * HWX + hw0 + col;
                    float2 v0 = make_float2(acc[mh * 16 + j * 4 + 0] + bet[mh][0],
                                            acc[mh * 16 + j * 4 + 1] + bet[mh][0]);
                    float2 v1 = make_float2(acc[mh * 16 + j * 4 + 2] + bet[mh][1],
                                            acc[mh * 16 + j * 4 + 3] + bet[mh][1]);
                    *(float2*)o0 = v0;
                    *(float2*)(o0 + (size_t)8 * HWX) = v1;
                }
            }
        }
    }
}

// ---------------- launch ----------------
extern "C" void kernel_launch(void* const* d_in, const int* in_sizes, int n_in,
                              void* d_out, int out_size) {
    const float* x      = (const float*)d_in[0];
    const float* weight = (const float*)d_in[1];
    const float* bias   = (const float*)d_in[2];
    float* out          = (float*)d_out;

    const int NS_SMEM  = (17472 + 16) * 4;        // 69952
    const int COV_SMEM = 3 * NCH * CP * 4;        // 52224
    const int WHT_SMEM = 2 * NCH * WP * 4;        // 69632
    cudaFuncSetAttribute(ns_kernel,     cudaFuncAttributeMaxDynamicSharedMemorySize, NS_SMEM);
    cudaFuncSetAttribute(cov_kernel,    cudaFuncAttributeMaxDynamicSharedMemorySize, COV_SMEM);
    cudaFuncSetAttribute(whiten_kernel, cudaFuncAttributeMaxDynamicSharedMemorySize, WHT_SMEM);

    zero_kernel<<<(G * NCH * NCH + 255) / 256, 256>>>();
    cov_kernel<<<G * NBLK, 256, COV_SMEM>>>(x);
    ns_kernel<<<G, 256, NS_SMEM>>>(weight, bias);
    whiten_kernel<<<G * NBLK, 256, WHT_SMEM>>>(x, out);
}